// round 13
// baseline (speedup 1.0000x reference)
#include <cuda_runtime.h>
#include <cstdint>

#define NN 8192
#define SCORE_TH 0.5f
#define W64 (NN / 64)     // 128 bitmap words per row
#define PT  256           // pair tile

// Global scratch (no allocations allowed)
__device__ float4        g_boxes_s[NN];
__device__ float         g_conf_s[NN];
__device__ float         g_area_s[NN];
__device__ unsigned char g_valid_s[NN];
// Transposed suppression bitmap: g_supT[g][j] bit (i-64g) set <=> i suppresses
// j (i < j). pair_kernel writes word (g,j) iff 64g < j and row j's tile is
// reached; bits at positions >= j-64g are always 0. Unwritten words are only
// ever read for rows that can never be kept (masked by valid/keep).
__device__ unsigned long long g_supT[W64][NN];   // 8 MB

// ---------------------------------------------------------------------------
// Kernel 1: stable-rank (stable argsort(-conf) by counting, bit-exact vs
// jnp) + fused output zero-fill. 256 blocks x 256 threads.
// ---------------------------------------------------------------------------
#define RT   256
#define EPB  32
#define QW   1024

__global__ void __launch_bounds__(RT) rank_kernel(const float* __restrict__ in,
                                                  float4* __restrict__ out4) {
    __shared__ unsigned int key[NN];   // 32 KB static
    __shared__ float smax[RT / 32];
    __shared__ int   spart[7 * EPB];

    const int tid = threadIdx.x;

    // fused zero-fill of output (10240 float4 over first 40 CTAs)
    {
        int zi = blockIdx.x * RT + tid;
        if (zi < (NN * 5) / 4) out4[zi] = make_float4(0.f, 0.f, 0.f, 0.f);
    }

    float m = 0.0f;                                   // conf uniform[0,1) >= 0
    #pragma unroll
    for (int k = 0; k < NN / RT; k++) {
        int j = tid + k * RT;
        float c = in[j * 5 + 4];
        key[j] = __float_as_uint(c);
        m = fmaxf(m, c);
    }
    #pragma unroll
    for (int o = 16; o; o >>= 1) m = fmaxf(m, __shfl_xor_sync(0xFFFFFFFFu, m, o));
    if ((tid & 31) == 0) smax[tid >> 5] = m;
    __syncthreads();
    float mx = smax[0];
    #pragma unroll
    for (int w = 1; w < RT / 32; w++) mx = fmaxf(mx, smax[w]);
    // deterministic fixed-order reduction -> identical mx in every block

    #pragma unroll
    for (int k = 0; k < NN / RT; k++) {
        int j = tid + k * RT;
        float c = __uint_as_float(key[j]);
        key[j] = ~__float_as_uint(__fdiv_rn(c, mx));  // IEEE div, matches jnp
    }
    __syncthreads();

    const int e = tid & (EPB - 1);
    const int q = tid >> 5;                 // slice 0..7
    const int i = blockIdx.x * EPB + e;
    const unsigned int Ki = key[i];
    const int lo = q * QW;
    const int up = lo + QW;

    int r = 0;
    const int b1 = min(up, max(lo, i));        // [lo,b1): j < i -> count <=
    #pragma unroll 8
    for (int j = lo; j < b1; j++) r += (key[j] <= Ki) ? 1 : 0;
    const int a2 = max(lo, min(up, i + 1));    // [a2,up): j > i -> count <
    #pragma unroll 8
    for (int j = a2; j < up; j++) r += (key[j] < Ki) ? 1 : 0;

    if (q > 0) spart[(q - 1) * EPB + e] = r;
    __syncthreads();

    if (q == 0) {
        int rank = r;
        #pragma unroll
        for (int t = 0; t < 7; t++) rank += spart[t * EPB + e];
        const float* bp = in + i * 5;
        float cx = bp[0], cy = bp[1], w = bp[2], h = bp[3];
        float hw = __fmul_rn(w, 0.5f);
        float hh = __fmul_rn(h, 0.5f);
        float x1 = __fsub_rn(cx, hw), y1 = __fsub_rn(cy, hh);
        float x2 = __fadd_rn(cx, hw), y2 = __fadd_rn(cy, hh);
        float conf = __uint_as_float(~Ki);
        g_boxes_s[rank] = make_float4(x1, y1, x2, y2);
        g_conf_s[rank]  = conf;
        g_area_s[rank]  = __fmul_rn(__fsub_rn(x2, x1), __fsub_rn(y2, y1));
        g_valid_s[rank] = (conf >= SCORE_TH) ? 1 : 0;
    }
}

// ---------------------------------------------------------------------------
// Kernel 2: suppression BITMAP build. valid[] is a sorted prefix, so tile
// early-outs use valid[j0]/valid[i0]; no global M needed. No atomics.
// ---------------------------------------------------------------------------
__global__ void __launch_bounds__(PT) pair_kernel() {
    __shared__ float4 sb[PT];
    __shared__ float  sa[PT];

    const int tid = threadIdx.x;
    const int j0 = blockIdx.x * PT;
    const int i0 = blockIdx.y * PT;
    // valid rows form a prefix: tile dead if its first row is invalid
    if (i0 > j0 || !g_valid_s[j0] || !g_valid_s[i0]) return;  // uniform

    int ii = i0 + tid;
    sb[tid] = g_boxes_s[ii];
    sa[tid] = g_area_s[ii];
    __syncthreads();                           // no barriers after this

    const int j = j0 + tid;
    if (!g_valid_s[j] || i0 >= j) return;      // per-thread

    const float4 bj = g_boxes_s[j];
    const float  aj = g_area_s[j];
    const int iend = min(j - i0, PT);          // test i0 .. i0+iend-1

    const int gbase = i0 >> 6;
    #pragma unroll
    for (int g = 0; g < 4; g++) {
        const int t0 = g * 64;
        const int t1 = min(iend, t0 + 64);
        if (t1 <= t0) break;
        unsigned long long mm = 0;
        for (int t = t0; t < t1; t++) {
            float4 bi = sb[t];
            float ix1 = fmaxf(bi.x, bj.x);
            float iy1 = fmaxf(bi.y, bj.y);
            float ix2 = fminf(bi.z, bj.z);
            float iy2 = fminf(bi.w, bj.w);
            float iw  = fmaxf(__fsub_rn(ix2, ix1), 0.0f);
            float ih  = fmaxf(__fsub_rn(iy2, iy1), 0.0f);
            float inter = __fmul_rn(iw, ih);
            float uni   = __fsub_rn(__fadd_rn(sa[t], aj), inter);
            // iou > 0.5  <=>  inter > 0.5*max(uni, 1e-9)
            unsigned long long hit =
                (inter > __fmul_rn(0.5f, fmaxf(uni, 1e-9f))) ? 1ull : 0ull;
            mm |= hit << (t - t0);
        }
        g_supT[gbase + g][j] = mm;             // unique writer, coalesced
    }
}

// ---------------------------------------------------------------------------
// Kernel 3: exact greedy resolve, word-sequential (64 rows/step), ZERO
// fixpoint iteration. Per step: 1024 threads gather cross-suppression bits
// (earlier words & FINAL keeps, shfl-OR reduced), then warp 0 resolves the
// word exactly via the ballot-greedy loop (kept rows clear their victims'
// candidate bits). Deterministic cost; no fallback needed.
// ---------------------------------------------------------------------------
__global__ void __launch_bounds__(1024) resolve_kernel(float* __restrict__ out) {
    __shared__ unsigned long long keepw[W64];  // 1 KB final keep bitmap
    __shared__ unsigned char crossb[64];       // per-row cross-suppressed bit
    __shared__ int scnt[32];
    __shared__ int sM;

    const int tid = threadIdx.x;

    // --- count M (valid rows form a prefix) + clear keep bitmap ---
    for (int k = tid; k < W64; k += 1024) keepw[k] = 0;
    int cnt = 0;
    #pragma unroll
    for (int k = 0; k < NN / 1024; k++)
        cnt += (g_valid_s[tid + k * 1024] != 0) ? 1 : 0;
    #pragma unroll
    for (int o = 16; o; o >>= 1) cnt += __shfl_xor_sync(0xFFFFFFFFu, cnt, o);
    if ((tid & 31) == 0) scnt[tid >> 5] = cnt;
    __syncthreads();
    if (tid == 0) {
        int s = 0;
        #pragma unroll
        for (int w = 0; w < 32; w++) s += scnt[w];
        sM = s;
    }
    __syncthreads();
    const int M = sM;
    const int NW = (M + 63) >> 6;

    const int jl = tid >> 4;                  // 0..63: row within word
    const int sl = tid & 15;                  // slice 0..15
    const int lane = tid & 31;

    for (int g = 0; g < NW; g++) {
        // --- gather cross-suppression for the 64 rows of word g ---
        const int j = (g << 6) + jl;
        unsigned int bit = 0;
        for (int gg = sl; gg < g; gg += 16)
            bit |= (g_supT[gg][j] & keepw[gg]) != 0ull ? 1u : 0u;
        #pragma unroll
        for (int o = 8; o; o >>= 1) bit |= __shfl_xor_sync(0xFFFFFFFFu, bit, o);
        if (sl == 0) crossb[jl] = (unsigned char)bit;
        __syncthreads();

        // --- warp 0: exact greedy within the word (two 32-row half-passes) ---
        if (tid < 32) {
            const int rlo = (g << 6) + lane;
            const int rhi = rlo + 32;
            // rowmask words (own word g); row 64g (lane 0) has no written word
            unsigned int rml = (lane > 0) ? (unsigned int)g_supT[g][rlo] : 0u;
            unsigned long long rmh = g_supT[g][rhi];
            bool al_lo = g_valid_s[rlo] && !crossb[lane];
            bool al_hi = g_valid_s[rhi] && !crossb[lane + 32];

            // lower half: greedy by ascending row
            unsigned int cand = __ballot_sync(0xFFFFFFFFu, al_lo);
            unsigned int keepm = 0;
            while (cand) {
                int b = __ffs(cand) - 1;
                keepm |= 1u << b;
                unsigned int vict = __ballot_sync(0xFFFFFFFFu, (rml >> b) & 1u);
                cand &= ~vict & ~(1u << b);
            }
            // upper half: apply lower keeps, then greedy
            unsigned int rmh_lo = (unsigned int)rmh;          // bits: rows 64g..+31
            unsigned int rmh_hi = (unsigned int)(rmh >> 32);  // bits: rows +32..
            bool al2 = al_hi && ((rmh_lo & keepm) == 0u);
            unsigned int cand2 = __ballot_sync(0xFFFFFFFFu, al2);
            unsigned int keepm2 = 0;
            while (cand2) {
                int b = __ffs(cand2) - 1;
                keepm2 |= 1u << b;
                unsigned int vict = __ballot_sync(0xFFFFFFFFu, (rmh_hi >> b) & 1u);
                cand2 &= ~vict & ~(1u << b);
            }
            if (lane == 0)
                keepw[g] = (unsigned long long)keepm |
                           ((unsigned long long)keepm2 << 32);
        }
        __syncthreads();
    }

    // --- emit kept rows (rank kernel zero-filled the output) ---
    #pragma unroll
    for (int k = 0; k < NN / 1024; k++) {
        int p = tid + k * 1024;
        if ((keepw[p >> 6] >> (p & 63)) & 1ull) {
            float4 b = g_boxes_s[p];
            float* o = out + p * 5;
            o[0] = b.x; o[1] = b.y; o[2] = b.z; o[3] = b.w;
            o[4] = g_conf_s[p];
        }
    }
}

// ---------------------------------------------------------------------------
extern "C" void kernel_launch(void* const* d_in, const int* in_sizes, int n_in,
                              void* d_out, int out_size) {
    const float* in = (const float*)d_in[0];
    float* out = (float*)d_out;

    rank_kernel<<<NN / EPB, RT>>>(in, (float4*)out);     // 256 x 256 (+zero)
    pair_kernel<<<dim3(NN / PT, NN / PT), PT>>>();       // 32 x 32 (early exit)
    resolve_kernel<<<1, 1024>>>(out);
}

// round 14
// speedup vs baseline: 1.2021x; 1.2021x over previous
#include <cuda_runtime.h>
#include <cstdint>

#define NN 8192
#define SCORE_TH 0.5f
#define W64 (NN / 64)     // 128 bitmap words
#define PT  256           // pair tile

typedef unsigned long long u64;

// Global scratch (no allocations allowed)
__device__ float4        g_boxes_s[NN];
__device__ float         g_conf_s[NN];
__device__ float         g_area_s[NN];
__device__ unsigned char g_valid_s[NN];
// Transposed suppression bitmap: g_supT[g][j] bit (i-64g) set <=> i suppresses
// j (i < j). Written for valid j and 64g < j; bits >= j-64g are 0. Unwritten
// words are only read for rows already dead (masked by valid/cross).
__device__ u64 g_supT[W64][NN];   // 8 MB

// ---------------------------------------------------------------------------
// Kernel 1: stable-rank (stable argsort(-conf) by counting, bit-exact vs
// jnp) + fused output zero-fill. 256 blocks x 512 threads, 16 scan slices.
// ---------------------------------------------------------------------------
#define RT   512
#define EPB  32
#define NSL  16
#define QW   (NN / NSL)   // 512 keys per slice

__global__ void __launch_bounds__(RT) rank_kernel(const float* __restrict__ in,
                                                  float4* __restrict__ out4) {
    __shared__ unsigned int key[NN];   // 32 KB static
    __shared__ float smax[RT / 32];
    __shared__ int   spart[(NSL - 1) * EPB];

    const int tid = threadIdx.x;

    // fused zero-fill of output (10240 float4 over first 20 CTAs)
    {
        int zi = blockIdx.x * RT + tid;
        if (zi < (NN * 5) / 4) out4[zi] = make_float4(0.f, 0.f, 0.f, 0.f);
    }

    float m = 0.0f;                                   // conf uniform[0,1) >= 0
    #pragma unroll
    for (int k = 0; k < NN / RT; k++) {
        int j = tid + k * RT;
        float c = in[j * 5 + 4];
        key[j] = __float_as_uint(c);
        m = fmaxf(m, c);
    }
    #pragma unroll
    for (int o = 16; o; o >>= 1) m = fmaxf(m, __shfl_xor_sync(0xFFFFFFFFu, m, o));
    if ((tid & 31) == 0) smax[tid >> 5] = m;
    __syncthreads();
    float mx = smax[0];
    #pragma unroll
    for (int w = 1; w < RT / 32; w++) mx = fmaxf(mx, smax[w]);
    // deterministic fixed-order reduction -> identical mx in every block

    #pragma unroll
    for (int k = 0; k < NN / RT; k++) {
        int j = tid + k * RT;
        float c = __uint_as_float(key[j]);
        key[j] = ~__float_as_uint(__fdiv_rn(c, mx));  // IEEE div, matches jnp
    }
    __syncthreads();

    const int e = tid & (EPB - 1);
    const int q = tid >> 5;                 // slice 0..15
    const int i = blockIdx.x * EPB + e;
    const unsigned int Ki = key[i];
    const int lo = q * QW;
    const int up = lo + QW;

    int r = 0;
    const int b1 = min(up, max(lo, i));        // [lo,b1): j < i -> count <=
    #pragma unroll 8
    for (int j = lo; j < b1; j++) r += (key[j] <= Ki) ? 1 : 0;
    const int a2 = max(lo, min(up, i + 1));    // [a2,up): j > i -> count <
    #pragma unroll 8
    for (int j = a2; j < up; j++) r += (key[j] < Ki) ? 1 : 0;

    if (q > 0) spart[(q - 1) * EPB + e] = r;
    __syncthreads();

    if (q == 0) {
        int rank = r;
        #pragma unroll
        for (int t = 0; t < NSL - 1; t++) rank += spart[t * EPB + e];
        const float* bp = in + i * 5;
        float cx = bp[0], cy = bp[1], w = bp[2], h = bp[3];
        float hw = __fmul_rn(w, 0.5f);
        float hh = __fmul_rn(h, 0.5f);
        float x1 = __fsub_rn(cx, hw), y1 = __fsub_rn(cy, hh);
        float x2 = __fadd_rn(cx, hw), y2 = __fadd_rn(cy, hh);
        float conf = __uint_as_float(~Ki);
        g_boxes_s[rank] = make_float4(x1, y1, x2, y2);
        g_conf_s[rank]  = conf;
        g_area_s[rank]  = __fmul_rn(__fsub_rn(x2, x1), __fsub_rn(y2, y1));
        g_valid_s[rank] = (conf >= SCORE_TH) ? 1 : 0;
    }
}

// ---------------------------------------------------------------------------
// Kernel 2: suppression BITMAP build (unchanged, proven). valid[] is a
// sorted prefix -> tile early-outs; no atomics, unique coalesced writers.
// ---------------------------------------------------------------------------
__global__ void __launch_bounds__(PT) pair_kernel() {
    __shared__ float4 sb[PT];
    __shared__ float  sa[PT];

    const int tid = threadIdx.x;
    const int j0 = blockIdx.x * PT;
    const int i0 = blockIdx.y * PT;
    if (i0 > j0 || !g_valid_s[j0] || !g_valid_s[i0]) return;  // uniform

    int ii = i0 + tid;
    sb[tid] = g_boxes_s[ii];
    sa[tid] = g_area_s[ii];
    __syncthreads();                           // no barriers after this

    const int j = j0 + tid;
    if (!g_valid_s[j] || i0 >= j) return;      // per-thread

    const float4 bj = g_boxes_s[j];
    const float  aj = g_area_s[j];
    const int iend = min(j - i0, PT);          // test i0 .. i0+iend-1

    const int gbase = i0 >> 6;
    #pragma unroll
    for (int g = 0; g < 4; g++) {
        const int t0 = g * 64;
        const int t1 = min(iend, t0 + 64);
        if (t1 <= t0) break;
        u64 mm = 0;
        for (int t = t0; t < t1; t++) {
            float4 bi = sb[t];
            float ix1 = fmaxf(bi.x, bj.x);
            float iy1 = fmaxf(bi.y, bj.y);
            float ix2 = fminf(bi.z, bj.z);
            float iy2 = fminf(bi.w, bj.w);
            float iw  = fmaxf(__fsub_rn(ix2, ix1), 0.0f);
            float ih  = fmaxf(__fsub_rn(iy2, iy1), 0.0f);
            float inter = __fmul_rn(iw, ih);
            float uni   = __fsub_rn(__fadd_rn(sa[t], aj), inter);
            // iou > 0.5  <=>  inter > 0.5*max(uni, 1e-9)
            u64 hit = (inter > __fmul_rn(0.5f, fmaxf(uni, 1e-9f))) ? 1ull : 0ull;
            mm |= hit << (t - t0);
        }
        g_supT[gbase + g][j] = mm;             // unique writer, coalesced
    }
}

// ---------------------------------------------------------------------------
// Kernel 3: exact greedy resolve. 8 steps of 512 rows; per step:
//   A) coalesced cross-suppression gather vs FINAL earlier keeps (warp = 32
//      consecutive rows, slice-uniform word index — the R12 mapping),
//   B) stage the block's 8 intra mask words into smem (coalesced),
//   C) warp 0 resolves all 8 words exactly: inter-word masks AND register
//      keep words (unrolled), intra-word ballot-greedy (proven in R13).
// 3 barriers/step, zero fixpoint iteration, unconditionally exact.
// ---------------------------------------------------------------------------
__global__ void __launch_bounds__(1024) resolve_kernel(float* __restrict__ out) {
    __shared__ u64 keepw[W64];                 //  1 KB final keep bitmap
    __shared__ u64 sA[2 * 512];                //  8 KB gather partials
    __shared__ u64 sm[8 * 512];                // 32 KB staged intra masks
    __shared__ unsigned char crossb[512];      // dead-row byte (cross|invalid)
    __shared__ int scnt[32];
    __shared__ int sM;

    const int tid = threadIdx.x;

    // --- count M (valid rows form a prefix) + clear keep bitmap ---
    for (int k = tid; k < W64; k += 1024) keepw[k] = 0;
    int cnt = 0;
    #pragma unroll
    for (int k = 0; k < NN / 1024; k++)
        cnt += (g_valid_s[tid + k * 1024] != 0) ? 1 : 0;
    #pragma unroll
    for (int o = 16; o; o >>= 1) cnt += __shfl_xor_sync(0xFFFFFFFFu, cnt, o);
    if ((tid & 31) == 0) scnt[tid >> 5] = cnt;
    __syncthreads();
    if (tid == 0) {
        int s = 0;
        #pragma unroll
        for (int w = 0; w < 32; w++) s += scnt[w];
        sM = s;
    }
    __syncthreads();
    const int M = sM;

    const int jl = tid & 511;
    const int sl = tid >> 9;                  // slice 0..1

    for (int b = 0; b < 8; b++) {
        if (b * 512 >= M) break;              // uniform; keepw stays 0
        const int j = b * 512 + jl;

        // --- A: cross gather (coalesced: warp = 32 consecutive j, same gg) ---
        u64 acc = 0;
        for (int gg = sl; gg < 8 * b; gg += 2)
            acc |= g_supT[gg][j] & keepw[gg];
        sA[sl * 512 + jl] = acc;

        // --- B: stage intra mask words (coalesced) ---
        #pragma unroll
        for (int k = 0; k < 4; k++) {
            int idx = k * 1024 + tid;
            sm[idx] = g_supT[8 * b + (idx >> 9)][b * 512 + (idx & 511)];
        }
        __syncthreads();

        if (tid < 512) {
            bool dead = ((sA[tid] | sA[512 + tid]) != 0ull) ||
                        (g_valid_s[b * 512 + tid] == 0);
            crossb[tid] = dead ? 1 : 0;
        }
        __syncthreads();

        // --- C: warp 0 resolves the 8 words exactly ---
        if (tid < 32) {
            const int lane = tid;
            u64 kw[8];
            #pragma unroll
            for (int w = 0; w < 8; w++) {
                const int rlo = w * 64 + lane;
                const int rhi = rlo + 32;
                // inter-word suppression from earlier keeps of this block
                u64 suplo = 0, suphi = 0;
                #pragma unroll
                for (int w2 = 0; w2 < 7; w2++) {
                    if (w2 < w) {
                        suplo |= sm[w2 * 512 + rlo] & kw[w2];
                        suphi |= sm[w2 * 512 + rhi] & kw[w2];
                    }
                }
                bool al_lo = (crossb[rlo] == 0) && (suplo == 0ull);
                bool al_hi = (crossb[rhi] == 0) && (suphi == 0ull);
                // own-word masks (row at word start has no written word)
                unsigned int rml = (lane > 0) ? (unsigned int)sm[w * 512 + rlo] : 0u;
                u64 rmh = sm[w * 512 + rhi];

                // lower half greedy
                unsigned int cand = __ballot_sync(0xFFFFFFFFu, al_lo);
                unsigned int keepm = 0;
                while (cand) {
                    int bb = __ffs(cand) - 1;
                    keepm |= 1u << bb;
                    unsigned int vict =
                        __ballot_sync(0xFFFFFFFFu, (rml >> bb) & 1u);
                    cand &= ~vict & ~(1u << bb);
                }
                // upper half: apply lower keeps, then greedy
                unsigned int rmh_lo = (unsigned int)rmh;
                unsigned int rmh_hi = (unsigned int)(rmh >> 32);
                bool al2 = al_hi && ((rmh_lo & keepm) == 0u);
                unsigned int cand2 = __ballot_sync(0xFFFFFFFFu, al2);
                unsigned int keepm2 = 0;
                while (cand2) {
                    int bb = __ffs(cand2) - 1;
                    keepm2 |= 1u << bb;
                    unsigned int vict =
                        __ballot_sync(0xFFFFFFFFu, (rmh_hi >> bb) & 1u);
                    cand2 &= ~vict & ~(1u << bb);
                }
                kw[w] = (u64)keepm | ((u64)keepm2 << 32);  // uniform across lanes
                if (lane == 0) keepw[8 * b + w] = kw[w];
            }
        }
        __syncthreads();
    }

    // --- emit kept rows (rank kernel zero-filled the output) ---
    #pragma unroll
    for (int k = 0; k < NN / 1024; k++) {
        int p = tid + k * 1024;
        if ((keepw[p >> 6] >> (p & 63)) & 1ull) {
            float4 b = g_boxes_s[p];
            float* o = out + p * 5;
            o[0] = b.x; o[1] = b.y; o[2] = b.z; o[3] = b.w;
            o[4] = g_conf_s[p];
        }
    }
}

// ---------------------------------------------------------------------------
extern "C" void kernel_launch(void* const* d_in, const int* in_sizes, int n_in,
                              void* d_out, int out_size) {
    const float* in = (const float*)d_in[0];
    float* out = (float*)d_out;

    rank_kernel<<<NN / EPB, RT>>>(in, (float4*)out);     // 256 x 512 (+zero)
    pair_kernel<<<dim3(NN / PT, NN / PT), PT>>>();       // 32 x 32 (early exit)
    resolve_kernel<<<1, 1024>>>(out);
}

// round 15
// speedup vs baseline: 3.4432x; 2.8644x over previous
#include <cuda_runtime.h>
#include <cstdint>

#define NN 8192
#define SCORE_TH 0.5f
#define W64 (NN / 64)     // 128 bitmap words
#define PT  256           // pair tile

typedef unsigned long long u64;

// Global scratch (no allocations allowed)
__device__ float4        g_boxes_s[NN];
__device__ float         g_conf_s[NN];
__device__ float         g_area_s[NN];
__device__ unsigned char g_valid_s[NN];
// Transposed suppression bitmap: g_supT[g][j] bit (i-64g) set <=> i suppresses
// j (i < j). Written for valid j and 64g < j; bits >= j-64g are 0. Unwritten
// words are only read for rows already dead (masked by valid/cross).
__device__ u64 g_supT[W64][NN];   // 8 MB

// ---------------------------------------------------------------------------
// Kernel 1: stable-rank (stable argsort(-conf) by counting, bit-exact vs
// jnp) + fused output zero-fill. 256 blocks x 256 threads (measured-best
// R13 config: 20.3us).
// ---------------------------------------------------------------------------
#define RT   256
#define EPB  32
#define QW   1024

__global__ void __launch_bounds__(RT) rank_kernel(const float* __restrict__ in,
                                                  float4* __restrict__ out4) {
    __shared__ unsigned int key[NN];   // 32 KB static
    __shared__ float smax[RT / 32];
    __shared__ int   spart[7 * EPB];

    const int tid = threadIdx.x;

    // fused zero-fill of output (10240 float4 over first 40 CTAs)
    {
        int zi = blockIdx.x * RT + tid;
        if (zi < (NN * 5) / 4) out4[zi] = make_float4(0.f, 0.f, 0.f, 0.f);
    }

    float m = 0.0f;                                   // conf uniform[0,1) >= 0
    #pragma unroll
    for (int k = 0; k < NN / RT; k++) {
        int j = tid + k * RT;
        float c = in[j * 5 + 4];
        key[j] = __float_as_uint(c);
        m = fmaxf(m, c);
    }
    #pragma unroll
    for (int o = 16; o; o >>= 1) m = fmaxf(m, __shfl_xor_sync(0xFFFFFFFFu, m, o));
    if ((tid & 31) == 0) smax[tid >> 5] = m;
    __syncthreads();
    float mx = smax[0];
    #pragma unroll
    for (int w = 1; w < RT / 32; w++) mx = fmaxf(mx, smax[w]);
    // deterministic fixed-order reduction -> identical mx in every block

    #pragma unroll
    for (int k = 0; k < NN / RT; k++) {
        int j = tid + k * RT;
        float c = __uint_as_float(key[j]);
        key[j] = ~__float_as_uint(__fdiv_rn(c, mx));  // IEEE div, matches jnp
    }
    __syncthreads();

    const int e = tid & (EPB - 1);
    const int q = tid >> 5;                 // slice 0..7
    const int i = blockIdx.x * EPB + e;
    const unsigned int Ki = key[i];
    const int lo = q * QW;
    const int up = lo + QW;

    int r = 0;
    const int b1 = min(up, max(lo, i));        // [lo,b1): j < i -> count <=
    #pragma unroll 8
    for (int j = lo; j < b1; j++) r += (key[j] <= Ki) ? 1 : 0;
    const int a2 = max(lo, min(up, i + 1));    // [a2,up): j > i -> count <
    #pragma unroll 8
    for (int j = a2; j < up; j++) r += (key[j] < Ki) ? 1 : 0;

    if (q > 0) spart[(q - 1) * EPB + e] = r;
    __syncthreads();

    if (q == 0) {
        int rank = r;
        #pragma unroll
        for (int t = 0; t < 7; t++) rank += spart[t * EPB + e];
        const float* bp = in + i * 5;
        float cx = bp[0], cy = bp[1], w = bp[2], h = bp[3];
        float hw = __fmul_rn(w, 0.5f);
        float hh = __fmul_rn(h, 0.5f);
        float x1 = __fsub_rn(cx, hw), y1 = __fsub_rn(cy, hh);
        float x2 = __fadd_rn(cx, hw), y2 = __fadd_rn(cy, hh);
        float conf = __uint_as_float(~Ki);
        g_boxes_s[rank] = make_float4(x1, y1, x2, y2);
        g_conf_s[rank]  = conf;
        g_area_s[rank]  = __fmul_rn(__fsub_rn(x2, x1), __fsub_rn(y2, y1));
        g_valid_s[rank] = (conf >= SCORE_TH) ? 1 : 0;
    }
}

// ---------------------------------------------------------------------------
// Kernel 2: suppression BITMAP build (unchanged, proven). valid[] is a
// sorted prefix -> tile early-outs; no atomics, unique coalesced writers.
// ---------------------------------------------------------------------------
__global__ void __launch_bounds__(PT) pair_kernel() {
    __shared__ float4 sb[PT];
    __shared__ float  sa[PT];

    const int tid = threadIdx.x;
    const int j0 = blockIdx.x * PT;
    const int i0 = blockIdx.y * PT;
    if (i0 > j0 || !g_valid_s[j0] || !g_valid_s[i0]) return;  // uniform

    int ii = i0 + tid;
    sb[tid] = g_boxes_s[ii];
    sa[tid] = g_area_s[ii];
    __syncthreads();                           // no barriers after this

    const int j = j0 + tid;
    if (!g_valid_s[j] || i0 >= j) return;      // per-thread

    const float4 bj = g_boxes_s[j];
    const float  aj = g_area_s[j];
    const int iend = min(j - i0, PT);          // test i0 .. i0+iend-1

    const int gbase = i0 >> 6;
    #pragma unroll
    for (int g = 0; g < 4; g++) {
        const int t0 = g * 64;
        const int t1 = min(iend, t0 + 64);
        if (t1 <= t0) break;
        u64 mm = 0;
        for (int t = t0; t < t1; t++) {
            float4 bi = sb[t];
            float ix1 = fmaxf(bi.x, bj.x);
            float iy1 = fmaxf(bi.y, bj.y);
            float ix2 = fminf(bi.z, bj.z);
            float iy2 = fminf(bi.w, bj.w);
            float iw  = fmaxf(__fsub_rn(ix2, ix1), 0.0f);
            float ih  = fmaxf(__fsub_rn(iy2, iy1), 0.0f);
            float inter = __fmul_rn(iw, ih);
            float uni   = __fsub_rn(__fadd_rn(sa[t], aj), inter);
            // iou > 0.5  <=>  inter > 0.5*max(uni, 1e-9)
            u64 hit = (inter > __fmul_rn(0.5f, fmaxf(uni, 1e-9f))) ? 1ull : 0ull;
            mm |= hit << (t - t0);
        }
        g_supT[gbase + g][j] = mm;             // unique writer, coalesced
    }
}

// ---------------------------------------------------------------------------
// Kernel 3: exact greedy resolve. 8 steps of 512 rows; per step:
//   A) coalesced cross-suppression gather vs FINAL earlier keeps,
//   B) stage the block's 8 intra mask words into smem (coalesced),
//   C) warp 0: Gauss-Seidel over the 8 words; WITHIN each word a bit-parallel
//      Jacobi on ballots (k' = cand & ~ballot(rowmask & k)) — settles rows in
//      chain-depth order (<= 64 iters, typically 2-4); stability == the
//      unique greedy fixpoint, so the result is unconditionally exact.
// 3 barriers/step, no per-keep serial chain, no fallback.
// ---------------------------------------------------------------------------
__global__ void __launch_bounds__(1024) resolve_kernel(float* __restrict__ out) {
    __shared__ u64 keepw[W64];                 //  1 KB final keep bitmap
    __shared__ u64 sA[2 * 512];                //  8 KB gather partials
    __shared__ u64 sm[8 * 512];                // 32 KB staged intra masks
    __shared__ unsigned char deadb[512];       // dead-row byte (cross|invalid)
    __shared__ int scnt[32];
    __shared__ int sM;

    const int tid = threadIdx.x;

    // --- count M (valid rows form a prefix) + clear keep bitmap ---
    for (int k = tid; k < W64; k += 1024) keepw[k] = 0;
    int cnt = 0;
    #pragma unroll
    for (int k = 0; k < NN / 1024; k++)
        cnt += (g_valid_s[tid + k * 1024] != 0) ? 1 : 0;
    #pragma unroll
    for (int o = 16; o; o >>= 1) cnt += __shfl_xor_sync(0xFFFFFFFFu, cnt, o);
    if ((tid & 31) == 0) scnt[tid >> 5] = cnt;
    __syncthreads();
    if (tid == 0) {
        int s = 0;
        #pragma unroll
        for (int w = 0; w < 32; w++) s += scnt[w];
        sM = s;
    }
    __syncthreads();
    const int M = sM;

    const int jl = tid & 511;
    const int sl = tid >> 9;                  // slice 0..1

    for (int b = 0; b < 8; b++) {
        if (b * 512 >= M) break;              // uniform; keepw stays 0
        const int j = b * 512 + jl;

        // --- A: cross gather (coalesced: warp = 32 consecutive j, same gg) ---
        u64 acc = 0;
        for (int gg = sl; gg < 8 * b; gg += 2)
            acc |= g_supT[gg][j] & keepw[gg];
        sA[sl * 512 + jl] = acc;

        // --- B: stage intra mask words (coalesced) ---
        #pragma unroll
        for (int k = 0; k < 4; k++) {
            int idx = k * 1024 + tid;
            sm[idx] = g_supT[8 * b + (idx >> 9)][b * 512 + (idx & 511)];
        }
        __syncthreads();

        if (tid < 512) {
            bool dead = ((sA[tid] | sA[512 + tid]) != 0ull) ||
                        (g_valid_s[b * 512 + tid] == 0);
            deadb[tid] = dead ? 1 : 0;
        }
        __syncthreads();

        // --- C: warp 0 resolves the 8 words (bit-parallel Jacobi) ---
        if (tid < 32) {
            const int lane = tid;
            u64 kw[8];
            #pragma unroll
            for (int w = 0; w < 8; w++) {
                const int rlo = w * 64 + lane;        // local row (low half)
                const int rhi = rlo + 32;             // local row (high half)
                // inter-word suppression from earlier (final) words of block
                u64 suplo = 0, suphi = 0;
                #pragma unroll
                for (int w2 = 0; w2 < 7; w2++) {
                    if (w2 < w) {
                        suplo |= sm[w2 * 512 + rlo] & kw[w2];
                        suphi |= sm[w2 * 512 + rhi] & kw[w2];
                    }
                }
                bool al_lo = (deadb[rlo] == 0) && (suplo == 0ull);
                bool al_hi = (deadb[rhi] == 0) && (suphi == 0ull);
                // own-word masks; word-start row (lane 0 low) has no written
                // word -> force 0. Bits >= own position are 0 by construction.
                u64 rm_lo = (lane > 0) ? sm[w * 512 + rlo] : 0ull;
                u64 rm_hi = sm[w * 512 + rhi];

                unsigned int candl = __ballot_sync(0xFFFFFFFFu, al_lo);
                unsigned int candh = __ballot_sync(0xFFFFFFFFu, al_hi);
                u64 cand = (u64)candl | ((u64)candh << 32);
                u64 k = cand;
                // Jacobi to the unique fixpoint: rows settle in chain-depth
                // order; terminates <= 64 iters (typically 2-4).
                while (true) {
                    bool s_lo = (rm_lo & k) != 0ull;
                    bool s_hi = (rm_hi & k) != 0ull;
                    unsigned int nl = __ballot_sync(0xFFFFFFFFu, !s_lo);
                    unsigned int nh = __ballot_sync(0xFFFFFFFFu, !s_hi);
                    u64 nk = cand & ((u64)nl | ((u64)nh << 32));
                    if (nk == k) break;
                    k = nk;
                }
                kw[w] = k;                            // uniform across lanes
                if (lane == 0) keepw[8 * b + w] = k;
            }
        }
        __syncthreads();
    }

    // --- emit kept rows (rank kernel zero-filled the output) ---
    #pragma unroll
    for (int k = 0; k < NN / 1024; k++) {
        int p = tid + k * 1024;
        if ((keepw[p >> 6] >> (p & 63)) & 1ull) {
            float4 b = g_boxes_s[p];
            float* o = out + p * 5;
            o[0] = b.x; o[1] = b.y; o[2] = b.z; o[3] = b.w;
            o[4] = g_conf_s[p];
        }
    }
}

// ---------------------------------------------------------------------------
extern "C" void kernel_launch(void* const* d_in, const int* in_sizes, int n_in,
                              void* d_out, int out_size) {
    const float* in = (const float*)d_in[0];
    float* out = (float*)d_out;

    rank_kernel<<<NN / EPB, RT>>>(in, (float4*)out);     // 256 x 256 (+zero)
    pair_kernel<<<dim3(NN / PT, NN / PT), PT>>>();       // 32 x 32 (early exit)
    resolve_kernel<<<1, 1024>>>(out);
}